// round 11
// baseline (speedup 1.0000x reference)
#include <cuda_runtime.h>
#include <cuda_fp16.h>
#include <math.h>
#include <stdint.h>

#define BB 8
#define TT 2048
#define DD 1024
#define EE 1024

#define RHB 80           // bytes per smem tile row (32 halves data + pad)
#define TILE_B 10240u    // 128 rows * 80B
#define SMEM3 (6 * 10240)  // 3 stages x (A + B)

// -------- scratch (device globals; allocation-free) --------
__device__ half  g_Xh [(size_t)BB * TT * DD];
__device__ half  g_WTh[(size_t)3 * DD * EE];
__device__ half  g_Qh [(size_t)BB * TT * EE];
__device__ half  g_Kh [(size_t)BB * TT * EE];
__device__ half  g_Vh [(size_t)BB * TT * EE];
__device__ half  g_VTh[(size_t)BB * EE * TT];
__device__ half  g_Eh [(size_t)BB * TT * TT];   // exp(scores), unnormalized
__device__ float g_psum[BB * 256];              // per 128x128 block sums
__device__ float g_inv_sum[BB];

// -------- helpers --------
__device__ __forceinline__ uint32_t s2u(const void* p) {
    return (uint32_t)__cvta_generic_to_shared(p);
}
__device__ __forceinline__ void cpasync16(uint32_t dst, const void* src) {
    asm volatile("cp.async.cg.shared.global [%0], [%1], 16;" :: "r"(dst), "l"(src));
}
__device__ __forceinline__ void cpcommit() {
    asm volatile("cp.async.commit_group;" ::: "memory");
}

#define LDSM4(r0, r1, r2, r3, addr) \
    asm volatile("ldmatrix.sync.aligned.m8n8.x4.shared.b16 {%0,%1,%2,%3}, [%4];" \
        : "=r"(r0), "=r"(r1), "=r"(r2), "=r"(r3) : "r"(addr))

__device__ __forceinline__ void mma16816(float* c, unsigned a0, unsigned a1,
                                         unsigned a2, unsigned a3,
                                         unsigned b0, unsigned b1) {
    asm volatile(
        "mma.sync.aligned.m16n8k16.row.col.f32.f16.f16.f32 "
        "{%0,%1,%2,%3}, {%4,%5,%6,%7}, {%8,%9}, {%0,%1,%2,%3};"
        : "+f"(c[0]), "+f"(c[1]), "+f"(c[2]), "+f"(c[3])
        : "r"(a0), "r"(a1), "r"(a2), "r"(a3), "r"(b0), "r"(b1));
}

// fill one 128x32-half tile (rows RHB bytes apart), coalesced 16B chunks
__device__ __forceinline__ void fill_tile(uint32_t dst, const half* src,
                                          int lds, int tid) {
#pragma unroll
    for (int it = 0; it < 2; ++it) {
        int idx = tid + it * 256;           // 0..511
        int row = idx >> 2, c = idx & 3;    // 4 x 16B per row
        cpasync16(dst + (uint32_t)(row * RHB + c * 16),
                  src + (size_t)row * lds + c * 8);
    }
}

// 3-stage pipelined fp16 GEMM body: 128x128 CTA tile, k-tile 32.
__device__ __forceinline__ void gemm_body(
    const half* __restrict__ A0, int lda,
    const half* __restrict__ B0, int ldb,
    int NK, uint32_t su, float acc[4][4][4], int tid)
{
    const int warp = tid >> 5, lane = tid & 31;
    const int wm = warp >> 2, wn = warp & 3;
    const uint32_t aoff = (uint32_t)((wm * 64 + (lane & 15)) * RHB + (lane >> 4) * 16);
    const uint32_t boff = (uint32_t)((wn * 32 + (lane & 7) + ((lane >> 4) << 3)) * RHB
                                     + ((lane >> 3) & 1) * 16);

    fill_tile(su, A0, lda, tid);
    fill_tile(su + TILE_B, B0, ldb, tid);
    cpcommit();
    if (NK > 1) {
        fill_tile(su + 2 * TILE_B, A0 + 32, lda, tid);
        fill_tile(su + 3 * TILE_B, B0 + 32, ldb, tid);
    }
    cpcommit();

    for (int kt = 0; kt < NK; ++kt) {
        asm volatile("cp.async.wait_group 1;" ::: "memory");
        __syncthreads();
        if (kt + 2 < NK) {
            uint32_t nb = su + (uint32_t)((kt + 2) % 3) * (2 * TILE_B);
            fill_tile(nb, A0 + (size_t)(kt + 2) * 32, lda, tid);
            fill_tile(nb + TILE_B, B0 + (size_t)(kt + 2) * 32, ldb, tid);
        }
        cpcommit();

        uint32_t As = su + (uint32_t)(kt % 3) * (2 * TILE_B);
        uint32_t Bs = As + TILE_B;
#pragma unroll
        for (int ks = 0; ks < 2; ++ks) {
            unsigned a[4][4];
#pragma unroll
            for (int mi = 0; mi < 4; ++mi)
                LDSM4(a[mi][0], a[mi][1], a[mi][2], a[mi][3],
                      As + aoff + (uint32_t)(mi * 16 * RHB + ks * 32));
            unsigned b[2][4];
#pragma unroll
            for (int np = 0; np < 2; ++np)
                LDSM4(b[np][0], b[np][1], b[np][2], b[np][3],
                      Bs + boff + (uint32_t)(np * 16 * RHB + ks * 32));
#pragma unroll
            for (int mi = 0; mi < 4; ++mi)
#pragma unroll
                for (int ni = 0; ni < 4; ++ni)
                    mma16816(acc[mi][ni],
                             a[mi][0], a[mi][1], a[mi][2], a[mi][3],
                             b[ni >> 1][(ni & 1) * 2], b[ni >> 1][(ni & 1) * 2 + 1]);
        }
    }
}

// ---------------------------------------------------------------------------
// prep kernels
// ---------------------------------------------------------------------------
__global__ __launch_bounds__(256) void conv_x(const float* __restrict__ x) {
    size_t i = ((size_t)blockIdx.x * 256 + threadIdx.x) * 8;
    float4 v0 = *reinterpret_cast<const float4*>(x + i);
    float4 v1 = *reinterpret_cast<const float4*>(x + i + 4);
    half2 h[4];
    h[0] = __floats2half2_rn(v0.x, v0.y);
    h[1] = __floats2half2_rn(v0.z, v0.w);
    h[2] = __floats2half2_rn(v1.x, v1.y);
    h[3] = __floats2half2_rn(v1.z, v1.w);
    *reinterpret_cast<uint4*>(g_Xh + i) = *reinterpret_cast<uint4*>(h);
}

// W^T as half: g_WTh[z][n][k] = (half)W_z[k][n]
__global__ __launch_bounds__(256) void transW_kernel(
    const float* __restrict__ W0, const float* __restrict__ W1,
    const float* __restrict__ W2)
{
    const float* W = (blockIdx.z == 0) ? W0 : (blockIdx.z == 1) ? W1 : W2;
    half* WT = g_WTh + (size_t)blockIdx.z * DD * EE;
    __shared__ float tile[32][33];
    int tx = threadIdx.x & 31, ty = threadIdx.x >> 5;
    int k0 = blockIdx.y * 32, n0 = blockIdx.x * 32;
#pragma unroll
    for (int j = 0; j < 4; ++j)
        tile[ty + j * 8][tx] = W[(size_t)(k0 + ty + j * 8) * EE + n0 + tx];
    __syncthreads();
#pragma unroll
    for (int j = 0; j < 4; ++j)
        WT[(size_t)(n0 + ty + j * 8) * DD + k0 + tx] = __float2half(tile[tx][ty + j * 8]);
}

// V^T half: g_VTh[b][n][t] = g_Vh[b][t][n]
__global__ __launch_bounds__(256) void transV_kernel()
{
    const half* V = g_Vh + (size_t)blockIdx.z * TT * EE;
    half* VT = g_VTh + (size_t)blockIdx.z * EE * TT;
    __shared__ half tile[32][34];
    int tx = threadIdx.x & 31, ty = threadIdx.x >> 5;
    int t0 = blockIdx.x * 32, n0 = blockIdx.y * 32;
#pragma unroll
    for (int j = 0; j < 4; ++j)
        tile[ty + j * 8][tx] = V[(size_t)(t0 + ty + j * 8) * EE + n0 + tx];
    __syncthreads();
#pragma unroll
    for (int j = 0; j < 4; ++j)
        VT[(size_t)(n0 + ty + j * 8) * TT + t0 + tx] = tile[tx][ty + j * 8];
}

// ---------------------------------------------------------------------------
// Projection: {Q,K,V}h[16384,1024] = Xh @ WTh_z^T + bias_z
// ---------------------------------------------------------------------------
__global__ __launch_bounds__(256, 2) void proj_h(
    const float* __restrict__ b0, const float* __restrict__ b1,
    const float* __restrict__ b2)
{
    extern __shared__ __align__(16) char sm[];
    __shared__ float sbias[128];

    const int tid = threadIdx.x;
    const int z = blockIdx.z;
    const int m0 = blockIdx.y * 128, n0 = blockIdx.x * 128;
    const float* bias = (z == 0) ? b0 : (z == 1) ? b1 : b2;
    half* __restrict__ C = (z == 0) ? g_Qh : (z == 1) ? g_Kh : g_Vh;

    if (tid < 128) sbias[tid] = bias[n0 + tid];

    float acc[4][4][4] = {};
    gemm_body(g_Xh + (size_t)m0 * DD, DD,
              g_WTh + (size_t)z * DD * EE + (size_t)n0 * DD, DD,
              DD / 32, s2u(sm), acc, tid);

    const int warp = tid >> 5, lane = tid & 31;
    const int wm = warp >> 2, wn = warp & 3;
    const int g = lane >> 2, tg = lane & 3;
#pragma unroll
    for (int mi = 0; mi < 4; ++mi) {
        int r0 = m0 + wm * 64 + mi * 16 + g;
#pragma unroll
        for (int ni = 0; ni < 4; ++ni) {
            int cl = wn * 32 + ni * 8 + 2 * tg;
            float bx = sbias[cl], by = sbias[cl + 1];
            int c = n0 + cl;
            *reinterpret_cast<half2*>(&C[(size_t)r0 * EE + c]) =
                __floats2half2_rn(acc[mi][ni][0] + bx, acc[mi][ni][1] + by);
            *reinterpret_cast<half2*>(&C[(size_t)(r0 + 8) * EE + c]) =
                __floats2half2_rn(acc[mi][ni][2] + bx, acc[mi][ni][3] + by);
        }
    }
}

// ---------------------------------------------------------------------------
// Scores+exp fused: E = exp((Q @ K^T)/32) (0 where masked), stored fp16;
// deterministic per-block partial sums -> g_psum. Global-softmax trick:
// out = (exp(S) @ V) / sum(exp(S)) — max subtraction not needed (|s| ~ 6).
// ---------------------------------------------------------------------------
__global__ __launch_bounds__(256, 2) void scores_h()
{
    const int bz = blockIdx.z;
    const int t0 = blockIdx.y * 128, s0 = blockIdx.x * 128;
    if (s0 > t0 + 127) return;  // fully masked: never read downstream

    extern __shared__ __align__(16) char sm[];
    __shared__ float red[256];

    const int tid = threadIdx.x;
    float acc[4][4][4] = {};
    gemm_body(g_Qh + ((size_t)bz * TT + t0) * EE, EE,
              g_Kh + ((size_t)bz * TT + s0) * EE, EE,
              EE / 32, s2u(sm), acc, tid);

    half* __restrict__ E = g_Eh + (size_t)bz * TT * TT;
    const int warp = tid >> 5, lane = tid & 31;
    const int wm = warp >> 2, wn = warp & 3;
    const int g = lane >> 2, tg = lane & 3;

    float lsum = 0.0f;
#pragma unroll
    for (int mi = 0; mi < 4; ++mi) {
        int r0 = t0 + wm * 64 + mi * 16 + g;
#pragma unroll
        for (int ni = 0; ni < 4; ++ni) {
            int c = s0 + wn * 32 + ni * 8 + 2 * tg;
#pragma unroll
            for (int hf = 0; hf < 2; ++hf) {
                int r = r0 + hf * 8;
                float v0 = (c     <= r) ? expf(acc[mi][ni][hf * 2 + 0] * 0.03125f) : 0.0f;
                float v1 = (c + 1 <= r) ? expf(acc[mi][ni][hf * 2 + 1] * 0.03125f) : 0.0f;
                lsum += v0 + v1;
                *reinterpret_cast<half2*>(&E[(size_t)r * TT + c]) =
                    __floats2half2_rn(v0, v1);
            }
        }
    }

    red[tid] = lsum;
    __syncthreads();
    for (int st = 128; st > 0; st >>= 1) {
        if (tid < st) red[tid] += red[tid + st];
        __syncthreads();
    }
    if (tid == 0) g_psum[bz * 256 + blockIdx.y * 16 + blockIdx.x] = red[0];
}

// deterministic final reduce over causal blocks only (bx <= by)
__global__ __launch_bounds__(256) void reduce_kernel()
{
    const int bz = blockIdx.x;
    const int tid = threadIdx.x;
    const int bx = tid & 15, by = tid >> 4;
    float s = (bx <= by) ? g_psum[bz * 256 + tid] : 0.0f;
    __shared__ float red[256];
    red[tid] = s;
    __syncthreads();
    for (int st = 128; st > 0; st >>= 1) {
        if (tid < st) red[tid] += red[tid + st];
        __syncthreads();
    }
    if (tid == 0) g_inv_sum[bz] = 1.0f / red[0];
}

// ---------------------------------------------------------------------------
// Output: O = (E @ V) * inv_sum; k-loop truncated at diagonal.
// ---------------------------------------------------------------------------
__global__ __launch_bounds__(256, 2) void out_h(float* __restrict__ O)
{
    const int bz = blockIdx.z;
    const int t0 = blockIdx.y * 128, n0 = blockIdx.x * 128;

    extern __shared__ __align__(16) char sm[];

    const int tid = threadIdx.x;
    float acc[4][4][4] = {};
    gemm_body(g_Eh + ((size_t)bz * TT + t0) * TT, TT,
              g_VTh + ((size_t)bz * EE + n0) * TT, TT,
              (t0 + 128) / 32, s2u(sm), acc, tid);

    const float inv = g_inv_sum[bz];
    const int warp = tid >> 5, lane = tid & 31;
    const int wm = warp >> 2, wn = warp & 3;
    const int g = lane >> 2, tg = lane & 3;
#pragma unroll
    for (int mi = 0; mi < 4; ++mi) {
        int r0 = t0 + wm * 64 + mi * 16 + g;
#pragma unroll
        for (int ni = 0; ni < 4; ++ni) {
            int c = n0 + wn * 32 + ni * 8 + 2 * tg;
            *reinterpret_cast<float2*>(&O[((size_t)bz * TT + r0) * EE + c]) =
                make_float2(acc[mi][ni][0] * inv, acc[mi][ni][1] * inv);
            *reinterpret_cast<float2*>(&O[((size_t)bz * TT + r0 + 8) * EE + c]) =
                make_float2(acc[mi][ni][2] * inv, acc[mi][ni][3] * inv);
        }
    }
}

// ---------------------------------------------------------------------------
extern "C" void kernel_launch(void* const* d_in, const int* in_sizes, int n_in,
                              void* d_out, int out_size)
{
    const float* x  = (const float*)d_in[0];
    const float* Wq = (const float*)d_in[1];
    const float* bq = (const float*)d_in[2];
    const float* Wk = (const float*)d_in[3];
    const float* bk = (const float*)d_in[4];
    const float* Wv = (const float*)d_in[5];
    const float* bv = (const float*)d_in[6];
    float* out = (float*)d_out;

    static bool attr_done = false;
    if (!attr_done) {
        cudaFuncSetAttribute(proj_h,
            cudaFuncAttributeMaxDynamicSharedMemorySize, SMEM3);
        cudaFuncSetAttribute(scores_h,
            cudaFuncAttributeMaxDynamicSharedMemorySize, SMEM3);
        cudaFuncSetAttribute(out_h,
            cudaFuncAttributeMaxDynamicSharedMemorySize, SMEM3);
        attr_done = true;
    }

    conv_x<<<8192, 256>>>(x);
    transW_kernel<<<dim3(32, 32, 3), 256>>>(Wq, Wk, Wv);

    proj_h<<<dim3(8, 128, 3), 256, SMEM3>>>(bq, bk, bv);
    transV_kernel<<<dim3(64, 32, 8), 256>>>();

    scores_h<<<dim3(16, 16, 8), 256, SMEM3>>>();
    reduce_kernel<<<BB, 256>>>();

    out_h<<<dim3(8, 16, 8), 256, SMEM3>>>(out);
}

// round 12
// speedup vs baseline: 1.5443x; 1.5443x over previous
#include <cuda_runtime.h>
#include <cuda_fp16.h>
#include <math.h>
#include <stdint.h>

#define BB 8
#define TT 2048
#define DD 1024
#define EE 1024

#define RHB 80           // bytes per smem tile row (32 halves data + pad)
#define TILE_B 10240u    // 128 rows * 80B
#define SMEM3 (6 * 10240)  // 3 stages x (A + B)

// -------- scratch (device globals; allocation-free) --------
__device__ half  g_Xh [(size_t)BB * TT * DD];
__device__ half  g_WTh[(size_t)3 * DD * EE];
__device__ half  g_Qh [(size_t)BB * TT * EE];
__device__ half  g_Kh [(size_t)BB * TT * EE];
__device__ half  g_Vh [(size_t)BB * TT * EE];
__device__ half  g_VTh[(size_t)BB * EE * TT];
__device__ half  g_Eh [(size_t)BB * TT * TT];   // exp(scores), unnormalized
__device__ float g_psum[BB * 256];              // per 128x128 block sums
__device__ float g_inv_sum[BB];

// -------- helpers --------
__device__ __forceinline__ uint32_t s2u(const void* p) {
    return (uint32_t)__cvta_generic_to_shared(p);
}
__device__ __forceinline__ void cpasync16(uint32_t dst, const void* src) {
    asm volatile("cp.async.cg.shared.global [%0], [%1], 16;" :: "r"(dst), "l"(src));
}
__device__ __forceinline__ void cpcommit() {
    asm volatile("cp.async.commit_group;" ::: "memory");
}

#define LDSM4(r0, r1, r2, r3, addr) \
    asm volatile("ldmatrix.sync.aligned.m8n8.x4.shared.b16 {%0,%1,%2,%3}, [%4];" \
        : "=r"(r0), "=r"(r1), "=r"(r2), "=r"(r3) : "r"(addr))

__device__ __forceinline__ void mma16816(float* c, unsigned a0, unsigned a1,
                                         unsigned a2, unsigned a3,
                                         unsigned b0, unsigned b1) {
    asm volatile(
        "mma.sync.aligned.m16n8k16.row.col.f32.f16.f16.f32 "
        "{%0,%1,%2,%3}, {%4,%5,%6,%7}, {%8,%9}, {%0,%1,%2,%3};"
        : "+f"(c[0]), "+f"(c[1]), "+f"(c[2]), "+f"(c[3])
        : "r"(a0), "r"(a1), "r"(a2), "r"(a3), "r"(b0), "r"(b1));
}

// fill one 128x32-half tile (rows RHB bytes apart), coalesced 16B chunks
__device__ __forceinline__ void fill_tile(uint32_t dst, const half* src,
                                          int lds, int tid) {
#pragma unroll
    for (int it = 0; it < 2; ++it) {
        int idx = tid + it * 256;           // 0..511
        int row = idx >> 2, c = idx & 3;    // 4 x 16B per row
        cpasync16(dst + (uint32_t)(row * RHB + c * 16),
                  src + (size_t)row * lds + c * 8);
    }
}

// 3-stage pipelined fp16 GEMM body: 128x128 CTA tile, k-tile 32.
__device__ __forceinline__ void gemm_body(
    const half* __restrict__ A0, int lda,
    const half* __restrict__ B0, int ldb,
    int NK, uint32_t su, float acc[4][4][4], int tid)
{
    const int warp = tid >> 5, lane = tid & 31;
    const int wm = warp >> 2, wn = warp & 3;
    const uint32_t aoff = (uint32_t)((wm * 64 + (lane & 15)) * RHB + (lane >> 4) * 16);
    const uint32_t boff = (uint32_t)((wn * 32 + (lane & 7) + ((lane >> 4) << 3)) * RHB
                                     + ((lane >> 3) & 1) * 16);

    fill_tile(su, A0, lda, tid);
    fill_tile(su + TILE_B, B0, ldb, tid);
    cpcommit();
    if (NK > 1) {
        fill_tile(su + 2 * TILE_B, A0 + 32, lda, tid);
        fill_tile(su + 3 * TILE_B, B0 + 32, ldb, tid);
    }
    cpcommit();

    for (int kt = 0; kt < NK; ++kt) {
        asm volatile("cp.async.wait_group 1;" ::: "memory");
        __syncthreads();
        if (kt + 2 < NK) {
            uint32_t nb = su + (uint32_t)((kt + 2) % 3) * (2 * TILE_B);
            fill_tile(nb, A0 + (size_t)(kt + 2) * 32, lda, tid);
            fill_tile(nb + TILE_B, B0 + (size_t)(kt + 2) * 32, ldb, tid);
        }
        cpcommit();

        uint32_t As = su + (uint32_t)(kt % 3) * (2 * TILE_B);
        uint32_t Bs = As + TILE_B;
#pragma unroll
        for (int ks = 0; ks < 2; ++ks) {
            unsigned a[4][4];
#pragma unroll
            for (int mi = 0; mi < 4; ++mi)
                LDSM4(a[mi][0], a[mi][1], a[mi][2], a[mi][3],
                      As + aoff + (uint32_t)(mi * 16 * RHB + ks * 32));
            unsigned b[2][4];
#pragma unroll
            for (int np = 0; np < 2; ++np)
                LDSM4(b[np][0], b[np][1], b[np][2], b[np][3],
                      Bs + boff + (uint32_t)(np * 16 * RHB + ks * 32));
#pragma unroll
            for (int mi = 0; mi < 4; ++mi)
#pragma unroll
                for (int ni = 0; ni < 4; ++ni)
                    mma16816(acc[mi][ni],
                             a[mi][0], a[mi][1], a[mi][2], a[mi][3],
                             b[ni >> 1][(ni & 1) * 2], b[ni >> 1][(ni & 1) * 2 + 1]);
        }
    }
}

// ---------------------------------------------------------------------------
// prep kernels
// ---------------------------------------------------------------------------
__global__ __launch_bounds__(256) void conv_x(const float* __restrict__ x) {
    size_t i = ((size_t)blockIdx.x * 256 + threadIdx.x) * 8;
    float4 v0 = *reinterpret_cast<const float4*>(x + i);
    float4 v1 = *reinterpret_cast<const float4*>(x + i + 4);
    half2 h[4];
    h[0] = __floats2half2_rn(v0.x, v0.y);
    h[1] = __floats2half2_rn(v0.z, v0.w);
    h[2] = __floats2half2_rn(v1.x, v1.y);
    h[3] = __floats2half2_rn(v1.z, v1.w);
    *reinterpret_cast<uint4*>(g_Xh + i) = *reinterpret_cast<uint4*>(h);
}

// W^T as half: g_WTh[z][n][k] = (half)W_z[k][n]
__global__ __launch_bounds__(256) void transW_kernel(
    const float* __restrict__ W0, const float* __restrict__ W1,
    const float* __restrict__ W2)
{
    const float* W = (blockIdx.z == 0) ? W0 : (blockIdx.z == 1) ? W1 : W2;
    half* WT = g_WTh + (size_t)blockIdx.z * DD * EE;
    __shared__ float tile[32][33];
    int tx = threadIdx.x & 31, ty = threadIdx.x >> 5;
    int k0 = blockIdx.y * 32, n0 = blockIdx.x * 32;
#pragma unroll
    for (int j = 0; j < 4; ++j)
        tile[ty + j * 8][tx] = W[(size_t)(k0 + ty + j * 8) * EE + n0 + tx];
    __syncthreads();
#pragma unroll
    for (int j = 0; j < 4; ++j)
        WT[(size_t)(n0 + ty + j * 8) * DD + k0 + tx] = __float2half(tile[tx][ty + j * 8]);
}

// V^T half: g_VTh[b][n][t] = g_Vh[b][t][n]
__global__ __launch_bounds__(256) void transV_kernel()
{
    const half* V = g_Vh + (size_t)blockIdx.z * TT * EE;
    half* VT = g_VTh + (size_t)blockIdx.z * EE * TT;
    __shared__ half tile[32][34];
    int tx = threadIdx.x & 31, ty = threadIdx.x >> 5;
    int t0 = blockIdx.x * 32, n0 = blockIdx.y * 32;
#pragma unroll
    for (int j = 0; j < 4; ++j)
        tile[ty + j * 8][tx] = V[(size_t)(t0 + ty + j * 8) * EE + n0 + tx];
    __syncthreads();
#pragma unroll
    for (int j = 0; j < 4; ++j)
        VT[(size_t)(n0 + ty + j * 8) * TT + t0 + tx] = tile[tx][ty + j * 8];
}

// ---------------------------------------------------------------------------
// Projection: {Q,K,V}h[16384,1024] = Xh @ WTh_z^T + bias_z
// ---------------------------------------------------------------------------
__global__ __launch_bounds__(256, 2) void proj_h(
    const float* __restrict__ b0, const float* __restrict__ b1,
    const float* __restrict__ b2)
{
    extern __shared__ __align__(16) char sm[];
    __shared__ float sbias[128];

    const int tid = threadIdx.x;
    const int z = blockIdx.z;
    const int m0 = blockIdx.y * 128, n0 = blockIdx.x * 128;
    const float* bias = (z == 0) ? b0 : (z == 1) ? b1 : b2;
    half* __restrict__ C = (z == 0) ? g_Qh : (z == 1) ? g_Kh : g_Vh;

    if (tid < 128) sbias[tid] = bias[n0 + tid];

    float acc[4][4][4] = {};
    gemm_body(g_Xh + (size_t)m0 * DD, DD,
              g_WTh + (size_t)z * DD * EE + (size_t)n0 * DD, DD,
              DD / 32, s2u(sm), acc, tid);

    const int warp = tid >> 5, lane = tid & 31;
    const int wm = warp >> 2, wn = warp & 3;
    const int g = lane >> 2, tg = lane & 3;
#pragma unroll
    for (int mi = 0; mi < 4; ++mi) {
        int r0 = m0 + wm * 64 + mi * 16 + g;
#pragma unroll
        for (int ni = 0; ni < 4; ++ni) {
            int cl = wn * 32 + ni * 8 + 2 * tg;
            float bx = sbias[cl], by = sbias[cl + 1];
            int c = n0 + cl;
            *reinterpret_cast<half2*>(&C[(size_t)r0 * EE + c]) =
                __floats2half2_rn(acc[mi][ni][0] + bx, acc[mi][ni][1] + by);
            *reinterpret_cast<half2*>(&C[(size_t)(r0 + 8) * EE + c]) =
                __floats2half2_rn(acc[mi][ni][2] + bx, acc[mi][ni][3] + by);
        }
    }
}

// ---------------------------------------------------------------------------
// Scores+exp fused: E = exp((Q @ K^T)/32) (0 where masked), stored fp16;
// deterministic per-block partial sums -> g_psum. Uses __expf (branch-free
// MUFU path) to keep epilogue register pressure under the 128-reg cap.
// ---------------------------------------------------------------------------
__global__ __launch_bounds__(256, 2) void scores_h()
{
    const int bz = blockIdx.z;
    const int t0 = blockIdx.y * 128, s0 = blockIdx.x * 128;
    if (s0 > t0 + 127) return;  // fully masked: never read downstream

    extern __shared__ __align__(16) char sm[];
    __shared__ float red[256];

    const int tid = threadIdx.x;
    float acc[4][4][4] = {};
    gemm_body(g_Qh + ((size_t)bz * TT + t0) * EE, EE,
              g_Kh + ((size_t)bz * TT + s0) * EE, EE,
              EE / 32, s2u(sm), acc, tid);

    half* __restrict__ E = g_Eh + (size_t)bz * TT * TT;
    const int warp = tid >> 5, lane = tid & 31;
    const int wm = warp >> 2, wn = warp & 3;
    const int g = lane >> 2, tg = lane & 3;

    float lsum = 0.0f;
#pragma unroll
    for (int mi = 0; mi < 4; ++mi) {
        int r0 = t0 + wm * 64 + mi * 16 + g;
#pragma unroll
        for (int ni = 0; ni < 4; ++ni) {
            int c = s0 + wn * 32 + ni * 8 + 2 * tg;
#pragma unroll
            for (int hf = 0; hf < 2; ++hf) {
                int r = r0 + hf * 8;
                float e0 = __expf(acc[mi][ni][hf * 2 + 0] * 0.03125f);
                float e1 = __expf(acc[mi][ni][hf * 2 + 1] * 0.03125f);
                e0 = (c     <= r) ? e0 : 0.0f;
                e1 = (c + 1 <= r) ? e1 : 0.0f;
                lsum += e0 + e1;
                *reinterpret_cast<half2*>(&E[(size_t)r * TT + c]) =
                    __floats2half2_rn(e0, e1);
            }
        }
    }

    red[tid] = lsum;
    __syncthreads();
    for (int st = 128; st > 0; st >>= 1) {
        if (tid < st) red[tid] += red[tid + st];
        __syncthreads();
    }
    if (tid == 0) g_psum[bz * 256 + blockIdx.y * 16 + blockIdx.x] = red[0];
}

// deterministic final reduce over causal blocks only (bx <= by)
__global__ __launch_bounds__(256) void reduce_kernel()
{
    const int bz = blockIdx.x;
    const int tid = threadIdx.x;
    const int bx = tid & 15, by = tid >> 4;
    float s = (bx <= by) ? g_psum[bz * 256 + tid] : 0.0f;
    __shared__ float red[256];
    red[tid] = s;
    __syncthreads();
    for (int st = 128; st > 0; st >>= 1) {
        if (tid < st) red[tid] += red[tid + st];
        __syncthreads();
    }
    if (tid == 0) g_inv_sum[bz] = 1.0f / red[0];
}

// ---------------------------------------------------------------------------
// Output: O = (E @ V) * inv_sum; k-loop truncated at diagonal.
// ---------------------------------------------------------------------------
__global__ __launch_bounds__(256, 2) void out_h(float* __restrict__ O)
{
    const int bz = blockIdx.z;
    const int t0 = blockIdx.y * 128, n0 = blockIdx.x * 128;

    extern __shared__ __align__(16) char sm[];

    const int tid = threadIdx.x;
    float acc[4][4][4] = {};
    gemm_body(g_Eh + ((size_t)bz * TT + t0) * TT, TT,
              g_VTh + ((size_t)bz * EE + n0) * TT, TT,
              (t0 + 128) / 32, s2u(sm), acc, tid);

    const float inv = g_inv_sum[bz];
    const int warp = tid >> 5, lane = tid & 31;
    const int wm = warp >> 2, wn = warp & 3;
    const int g = lane >> 2, tg = lane & 3;
#pragma unroll
    for (int mi = 0; mi < 4; ++mi) {
        int r0 = t0 + wm * 64 + mi * 16 + g;
#pragma unroll
        for (int ni = 0; ni < 4; ++ni) {
            int c = n0 + wn * 32 + ni * 8 + 2 * tg;
            *reinterpret_cast<float2*>(&O[((size_t)bz * TT + r0) * EE + c]) =
                make_float2(acc[mi][ni][0] * inv, acc[mi][ni][1] * inv);
            *reinterpret_cast<float2*>(&O[((size_t)bz * TT + r0 + 8) * EE + c]) =
                make_float2(acc[mi][ni][2] * inv, acc[mi][ni][3] * inv);
        }
    }
}

// ---------------------------------------------------------------------------
extern "C" void kernel_launch(void* const* d_in, const int* in_sizes, int n_in,
                              void* d_out, int out_size)
{
    const float* x  = (const float*)d_in[0];
    const float* Wq = (const float*)d_in[1];
    const float* bq = (const float*)d_in[2];
    const float* Wk = (const float*)d_in[3];
    const float* bk = (const float*)d_in[4];
    const float* Wv = (const float*)d_in[5];
    const float* bv = (const float*)d_in[6];
    float* out = (float*)d_out;

    static bool attr_done = false;
    if (!attr_done) {
        cudaFuncSetAttribute(proj_h,
            cudaFuncAttributeMaxDynamicSharedMemorySize, SMEM3);
        cudaFuncSetAttribute(scores_h,
            cudaFuncAttributeMaxDynamicSharedMemorySize, SMEM3);
        cudaFuncSetAttribute(out_h,
            cudaFuncAttributeMaxDynamicSharedMemorySize, SMEM3);
        attr_done = true;
    }

    conv_x<<<8192, 256>>>(x);
    transW_kernel<<<dim3(32, 32, 3), 256>>>(Wq, Wk, Wv);

    proj_h<<<dim3(8, 128, 3), 256, SMEM3>>>(bq, bk, bv);
    transV_kernel<<<dim3(64, 32, 8), 256>>>();

    scores_h<<<dim3(16, 16, 8), 256, SMEM3>>>();
    reduce_kernel<<<BB, 256>>>();

    out_h<<<dim3(8, 16, 8), 256, SMEM3>>>(out);
}

// round 13
// speedup vs baseline: 1.6818x; 1.0890x over previous
#include <cuda_runtime.h>
#include <cuda_fp16.h>
#include <math.h>
#include <stdint.h>

#define BB 8
#define TT 2048
#define DD 1024
#define EE 1024

#define RHB 144          // bytes per smem tile row (64 halves data + 16B pad)
#define TILE_B 18432u    // 128 rows * 144B
#define SMEM2 (4 * 18432)  // 2 stages x (A + B)

// -------- scratch (device globals; allocation-free) --------
__device__ half  g_Xh [(size_t)BB * TT * DD];
__device__ half  g_WTh[(size_t)3 * DD * EE];
__device__ half  g_Qh [(size_t)BB * TT * EE];
__device__ half  g_Kh [(size_t)BB * TT * EE];
__device__ half  g_Vh [(size_t)BB * TT * EE];
__device__ half  g_VTh[(size_t)BB * EE * TT];
__device__ half  g_Eh [(size_t)BB * TT * TT];   // exp(scores), unnormalized
__device__ float g_psum[BB * 256];              // per 128x128 block sums
__device__ float g_inv_sum[BB];

// -------- helpers --------
__device__ __forceinline__ uint32_t s2u(const void* p) {
    return (uint32_t)__cvta_generic_to_shared(p);
}
__device__ __forceinline__ void cpasync16(uint32_t dst, const void* src) {
    asm volatile("cp.async.cg.shared.global [%0], [%1], 16;" :: "r"(dst), "l"(src));
}
__device__ __forceinline__ void cpcommit() {
    asm volatile("cp.async.commit_group;" ::: "memory");
}
__device__ __forceinline__ void cpwait0() {
    asm volatile("cp.async.wait_group 0;" ::: "memory");
}

#define LDSM4(r0, r1, r2, r3, addr) \
    asm volatile("ldmatrix.sync.aligned.m8n8.x4.shared.b16 {%0,%1,%2,%3}, [%4];" \
        : "=r"(r0), "=r"(r1), "=r"(r2), "=r"(r3) : "r"(addr))

__device__ __forceinline__ void mma16816(float* c, unsigned a0, unsigned a1,
                                         unsigned a2, unsigned a3,
                                         unsigned b0, unsigned b1) {
    asm volatile(
        "mma.sync.aligned.m16n8k16.row.col.f32.f16.f16.f32 "
        "{%0,%1,%2,%3}, {%4,%5,%6,%7}, {%8,%9}, {%0,%1,%2,%3};"
        : "+f"(c[0]), "+f"(c[1]), "+f"(c[2]), "+f"(c[3])
        : "r"(a0), "r"(a1), "r"(a2), "r"(a3), "r"(b0), "r"(b1));
}

// fill one 128x64-half tile (rows RHB bytes apart), coalesced 16B chunks
__device__ __forceinline__ void fill_tile(uint32_t dst, const half* src,
                                          int lds, int tid) {
#pragma unroll
    for (int it = 0; it < 4; ++it) {
        int idx = tid + it * 256;           // 0..1023
        int row = idx >> 3, c = idx & 7;    // 8 x 16B per row
        cpasync16(dst + (uint32_t)(row * RHB + c * 16),
                  src + (size_t)row * lds + c * 8);
    }
}

// 2-stage pipelined fp16 GEMM body: 128x128 CTA tile, k-tile 64.
// smem: stage s at su + s*2*TILE_B, layout [A|B].
__device__ __forceinline__ void gemm_body(
    const half* __restrict__ A0, int lda,
    const half* __restrict__ B0, int ldb,
    int NK, uint32_t su, float acc[4][4][4], int tid)
{
    const int warp = tid >> 5, lane = tid & 31;
    const int wm = warp >> 2, wn = warp & 3;
    const uint32_t aoff = (uint32_t)((wm * 64 + (lane & 15)) * RHB + (lane >> 4) * 16);
    const uint32_t boff = (uint32_t)((wn * 32 + (lane & 7) + ((lane >> 4) << 3)) * RHB
                                     + ((lane >> 3) & 1) * 16);

    fill_tile(su, A0, lda, tid);
    fill_tile(su + TILE_B, B0, ldb, tid);
    cpcommit();

    for (int kt = 0; kt < NK; ++kt) {
        cpwait0();
        __syncthreads();
        if (kt + 1 < NK) {
            uint32_t nb = su + (uint32_t)((kt + 1) & 1) * (2 * TILE_B);
            fill_tile(nb, A0 + (size_t)(kt + 1) * 64, lda, tid);
            fill_tile(nb + TILE_B, B0 + (size_t)(kt + 1) * 64, ldb, tid);
        }
        cpcommit();

        uint32_t As = su + (uint32_t)(kt & 1) * (2 * TILE_B);
        uint32_t Bs = As + TILE_B;
#pragma unroll
        for (int ks = 0; ks < 4; ++ks) {
            unsigned a[4][4];
#pragma unroll
            for (int mi = 0; mi < 4; ++mi)
                LDSM4(a[mi][0], a[mi][1], a[mi][2], a[mi][3],
                      As + aoff + (uint32_t)(mi * 16 * RHB + ks * 32));
            unsigned b[2][4];
#pragma unroll
            for (int np = 0; np < 2; ++np)
                LDSM4(b[np][0], b[np][1], b[np][2], b[np][3],
                      Bs + boff + (uint32_t)(np * 16 * RHB + ks * 32));
#pragma unroll
            for (int mi = 0; mi < 4; ++mi)
#pragma unroll
                for (int ni = 0; ni < 4; ++ni)
                    mma16816(acc[mi][ni],
                             a[mi][0], a[mi][1], a[mi][2], a[mi][3],
                             b[ni >> 1][(ni & 1) * 2], b[ni >> 1][(ni & 1) * 2 + 1]);
        }
        __syncthreads();
    }
}

// ---------------------------------------------------------------------------
// prep kernels
// ---------------------------------------------------------------------------
__global__ __launch_bounds__(256) void conv_x(const float* __restrict__ x) {
    size_t i = ((size_t)blockIdx.x * 256 + threadIdx.x) * 8;
    float4 v0 = *reinterpret_cast<const float4*>(x + i);
    float4 v1 = *reinterpret_cast<const float4*>(x + i + 4);
    half2 h[4];
    h[0] = __floats2half2_rn(v0.x, v0.y);
    h[1] = __floats2half2_rn(v0.z, v0.w);
    h[2] = __floats2half2_rn(v1.x, v1.y);
    h[3] = __floats2half2_rn(v1.z, v1.w);
    *reinterpret_cast<uint4*>(g_Xh + i) = *reinterpret_cast<uint4*>(h);
}

// W^T as half: g_WTh[z][n][k] = (half)W_z[k][n]
__global__ __launch_bounds__(256) void transW_kernel(
    const float* __restrict__ W0, const float* __restrict__ W1,
    const float* __restrict__ W2)
{
    const float* W = (blockIdx.z == 0) ? W0 : (blockIdx.z == 1) ? W1 : W2;
    half* WT = g_WTh + (size_t)blockIdx.z * DD * EE;
    __shared__ float tile[32][33];
    int tx = threadIdx.x & 31, ty = threadIdx.x >> 5;
    int k0 = blockIdx.y * 32, n0 = blockIdx.x * 32;
#pragma unroll
    for (int j = 0; j < 4; ++j)
        tile[ty + j * 8][tx] = W[(size_t)(k0 + ty + j * 8) * EE + n0 + tx];
    __syncthreads();
#pragma unroll
    for (int j = 0; j < 4; ++j)
        WT[(size_t)(n0 + ty + j * 8) * DD + k0 + tx] = __float2half(tile[tx][ty + j * 8]);
}

// V^T half: g_VTh[b][n][t] = g_Vh[b][t][n]
__global__ __launch_bounds__(256) void transV_kernel()
{
    const half* V = g_Vh + (size_t)blockIdx.z * TT * EE;
    half* VT = g_VTh + (size_t)blockIdx.z * EE * TT;
    __shared__ half tile[32][34];
    int tx = threadIdx.x & 31, ty = threadIdx.x >> 5;
    int t0 = blockIdx.x * 32, n0 = blockIdx.y * 32;
#pragma unroll
    for (int j = 0; j < 4; ++j)
        tile[ty + j * 8][tx] = V[(size_t)(t0 + ty + j * 8) * EE + n0 + tx];
    __syncthreads();
#pragma unroll
    for (int j = 0; j < 4; ++j)
        VT[(size_t)(n0 + ty + j * 8) * TT + t0 + tx] = tile[tx][ty + j * 8];
}

// ---------------------------------------------------------------------------
// Projection: {Q,K,V}h[16384,1024] = Xh @ WTh_z^T + bias_z
// ---------------------------------------------------------------------------
__global__ __launch_bounds__(256, 2) void proj_h(
    const float* __restrict__ b0, const float* __restrict__ b1,
    const float* __restrict__ b2)
{
    extern __shared__ __align__(16) char sm[];
    __shared__ float sbias[128];

    const int tid = threadIdx.x;
    const int z = blockIdx.z;
    const int m0 = blockIdx.y * 128, n0 = blockIdx.x * 128;
    const float* bias = (z == 0) ? b0 : (z == 1) ? b1 : b2;
    half* __restrict__ C = (z == 0) ? g_Qh : (z == 1) ? g_Kh : g_Vh;

    if (tid < 128) sbias[tid] = bias[n0 + tid];

    float acc[4][4][4] = {};
    gemm_body(g_Xh + (size_t)m0 * DD, DD,
              g_WTh + (size_t)z * DD * EE + (size_t)n0 * DD, DD,
              DD / 64, s2u(sm), acc, tid);

    const int warp = tid >> 5, lane = tid & 31;
    const int wm = warp >> 2, wn = warp & 3;
    const int g = lane >> 2, tg = lane & 3;
#pragma unroll
    for (int mi = 0; mi < 4; ++mi) {
        int r0 = m0 + wm * 64 + mi * 16 + g;
#pragma unroll
        for (int ni = 0; ni < 4; ++ni) {
            int cl = wn * 32 + ni * 8 + 2 * tg;
            float bx = sbias[cl], by = sbias[cl + 1];
            int c = n0 + cl;
            *reinterpret_cast<half2*>(&C[(size_t)r0 * EE + c]) =
                __floats2half2_rn(acc[mi][ni][0] + bx, acc[mi][ni][1] + by);
            *reinterpret_cast<half2*>(&C[(size_t)(r0 + 8) * EE + c]) =
                __floats2half2_rn(acc[mi][ni][2] + bx, acc[mi][ni][3] + by);
        }
    }
}

// ---------------------------------------------------------------------------
// Scores+exp fused: E = exp((Q @ K^T)/32) (0 where masked), stored fp16;
// deterministic per-block partial sums -> g_psum. __expf = branch-free MUFU.
// ---------------------------------------------------------------------------
__global__ __launch_bounds__(256, 2) void scores_h()
{
    const int bz = blockIdx.z;
    const int t0 = blockIdx.y * 128, s0 = blockIdx.x * 128;
    if (s0 > t0 + 127) return;  // fully masked: never read downstream

    extern __shared__ __align__(16) char sm[];
    __shared__ float red[256];

    const int tid = threadIdx.x;
    float acc[4][4][4] = {};
    gemm_body(g_Qh + ((size_t)bz * TT + t0) * EE, EE,
              g_Kh + ((size_t)bz * TT + s0) * EE, EE,
              EE / 64, s2u(sm), acc, tid);

    half* __restrict__ E = g_Eh + (size_t)bz * TT * TT;
    const int warp = tid >> 5, lane = tid & 31;
    const int wm = warp >> 2, wn = warp & 3;
    const int g = lane >> 2, tg = lane & 3;

    float lsum = 0.0f;
#pragma unroll
    for (int mi = 0; mi < 4; ++mi) {
        int r0 = t0 + wm * 64 + mi * 16 + g;
#pragma unroll
        for (int ni = 0; ni < 4; ++ni) {
            int c = s0 + wn * 32 + ni * 8 + 2 * tg;
#pragma unroll
            for (int hf = 0; hf < 2; ++hf) {
                int r = r0 + hf * 8;
                float e0 = __expf(acc[mi][ni][hf * 2 + 0] * 0.03125f);
                float e1 = __expf(acc[mi][ni][hf * 2 + 1] * 0.03125f);
                e0 = (c     <= r) ? e0 : 0.0f;
                e1 = (c + 1 <= r) ? e1 : 0.0f;
                lsum += e0 + e1;
                *reinterpret_cast<half2*>(&E[(size_t)r * TT + c]) =
                    __floats2half2_rn(e0, e1);
            }
        }
    }

    red[tid] = lsum;
    __syncthreads();
    for (int st = 128; st > 0; st >>= 1) {
        if (tid < st) red[tid] += red[tid + st];
        __syncthreads();
    }
    if (tid == 0) g_psum[bz * 256 + blockIdx.y * 16 + blockIdx.x] = red[0];
}

// deterministic final reduce over causal blocks only (bx <= by)
__global__ __launch_bounds__(256) void reduce_kernel()
{
    const int bz = blockIdx.x;
    const int tid = threadIdx.x;
    const int bx = tid & 15, by = tid >> 4;
    float s = (bx <= by) ? g_psum[bz * 256 + tid] : 0.0f;
    __shared__ float red[256];
    red[tid] = s;
    __syncthreads();
    for (int st = 128; st > 0; st >>= 1) {
        if (tid < st) red[tid] += red[tid + st];
        __syncthreads();
    }
    if (tid == 0) g_inv_sum[bz] = 1.0f / red[0];
}

// ---------------------------------------------------------------------------
// Output: O = (E @ V) * inv_sum; k-loop truncated at diagonal.
// ---------------------------------------------------------------------------
__global__ __launch_bounds__(256, 2) void out_h(float* __restrict__ O)
{
    const int bz = blockIdx.z;
    const int t0 = blockIdx.y * 128, n0 = blockIdx.x * 128;

    extern __shared__ __align__(16) char sm[];

    const int tid = threadIdx.x;
    float acc[4][4][4] = {};
    gemm_body(g_Eh + ((size_t)bz * TT + t0) * TT, TT,
              g_VTh + ((size_t)bz * EE + n0) * TT, TT,
              (t0 + 128) / 64, s2u(sm), acc, tid);

    const float inv = g_inv_sum[bz];
    const int warp = tid >> 5, lane = tid & 31;
    const int wm = warp >> 2, wn = warp & 3;
    const int g = lane >> 2, tg = lane & 3;
#pragma unroll
    for (int mi = 0; mi < 4; ++mi) {
        int r0 = t0 + wm * 64 + mi * 16 + g;
#pragma unroll
        for (int ni = 0; ni < 4; ++ni) {
            int c = n0 + wn * 32 + ni * 8 + 2 * tg;
            *reinterpret_cast<float2*>(&O[((size_t)bz * TT + r0) * EE + c]) =
                make_float2(acc[mi][ni][0] * inv, acc[mi][ni][1] * inv);
            *reinterpret_cast<float2*>(&O[((size_t)bz * TT + r0 + 8) * EE + c]) =
                make_float2(acc[mi][ni][2] * inv, acc[mi][ni][3] * inv);
        }
    }
}

// ---------------------------------------------------------------------------
extern "C" void kernel_launch(void* const* d_in, const int* in_sizes, int n_in,
                              void* d_out, int out_size)
{
    const float* x  = (const float*)d_in[0];
    const float* Wq = (const float*)d_in[1];
    const float* bq = (const float*)d_in[2];
    const float* Wk = (const float*)d_in[3];
    const float* bk = (const float*)d_in[4];
    const float* Wv = (const float*)d_in[5];
    const float* bv = (const float*)d_in[6];
    float* out = (float*)d_out;

    static bool attr_done = false;
    if (!attr_done) {
        cudaFuncSetAttribute(proj_h,
            cudaFuncAttributeMaxDynamicSharedMemorySize, SMEM2);
        cudaFuncSetAttribute(scores_h,
            cudaFuncAttributeMaxDynamicSharedMemorySize, SMEM2);
        cudaFuncSetAttribute(out_h,
            cudaFuncAttributeMaxDynamicSharedMemorySize, SMEM2);
        attr_done = true;
    }

    conv_x<<<8192, 256>>>(x);
    transW_kernel<<<dim3(32, 32, 3), 256>>>(Wq, Wk, Wv);

    proj_h<<<dim3(8, 128, 3), 256, SMEM2>>>(bq, bk, bv);
    transV_kernel<<<dim3(64, 32, 8), 256>>>();

    scores_h<<<dim3(16, 16, 8), 256, SMEM2>>>();
    reduce_kernel<<<BB, 256>>>();

    out_h<<<dim3(8, 16, 8), 256, SMEM2>>>(out);
}